// round 12
// baseline (speedup 1.0000x reference)
#include <cuda_runtime.h>
#include <mma.h>
#include <math.h>
#include <stdint.h>

using namespace nvcuda;

#define S_LEN  128
#define NBATCH 2048
#define HID    128
#define G4     512
#define OUTDIM 128
#define NH     (NBATCH*HID)
#define M_ALL  (S_LEN*NBATCH)

#define XPITCH 132                        // xg/proj staging pitch (128+4)
#define WP     132                        // persist W / h pitch
#define PP     68                         // park pitch (gate-major rows of 64 samples)

// persist smem map (float offsets)
#define F_W    0                          // [128][132] W_hh slice
#define F_AH   (128*132)                  // [64][132]  h(s-1) tile
#define F_PA   (F_AH + 64*132)            // [128][68]  park, K-half A
#define F_PB   (F_PA + 128*68)            // [128][68]  park, K-half B
#define F_BIAS (F_PB + 128*68)            // [128]
#define STEP_SMEM ((F_BIAS + 128)*4)      // 171520 B

#define GEMM_SMEM ((128 + 64)*XPITCH*4)   // 101376 B (xg + proj kernels)

#define CLUSTER_SYNC() do { \
    asm volatile("barrier.cluster.arrive.aligned;" ::: "memory"); \
    asm volatile("barrier.cluster.wait.aligned;"   ::: "memory"); \
} while (0)

// ---------------- static device scratch (no cudaMalloc anywhere) ----------------
__device__ float g_xg  [(size_t)M_ALL*G4];    // x·W_ih^T for all steps, packed gate cols
__device__ float g_hist[(size_t)M_ALL*HID];   // h_t history (tf32-rounded) — h exchange medium
__device__ float g_Wih_p[G4*HID];             // packed W_ih, tf32-rounded
__device__ float g_Whh_p[G4*HID];             // packed W_hh, tf32-rounded
__device__ float g_Wout_p[OUTDIM*HID];        // W_out, tf32-rounded
__device__ float g_bp[G4];                    // b_ih + b_hh, packed row order

__device__ __forceinline__ float to_tf32(float x) {
    unsigned r;
    asm("cvt.rna.tf32.f32 %0, %1;" : "=r"(r) : "f"(x));
    return __uint_as_float(r);
}
__device__ __forceinline__ float fsigm(float v) {
    return __fdividef(1.0f, 1.0f + __expf(-v));
}
__device__ __forceinline__ float ftanh(float v) {
    return 1.0f - 2.0f*__fdividef(1.0f, 1.0f + __expf(2.0f*v));
}

// Pack: packed row r = hb*128 + gate*32 + j  <->  orig row gate*128 + hb*32 + j.
__global__ void pack_kernel(const float* __restrict__ W_ih, const float* __restrict__ W_hh,
                            const float* __restrict__ b_ih, const float* __restrict__ b_hh,
                            const float* __restrict__ W_out) {
    int idx = blockIdx.x*256 + threadIdx.x;      // 65536 = 512 rows * 128 k
    int row = idx >> 7;
    int k   = idx & 127;
    int hb = row >> 7, rem = row & 127, gate = rem >> 5, j = rem & 31;
    int orow = gate*128 + hb*32 + j;
    g_Wih_p[row*HID + k] = to_tf32(W_ih[orow*HID + k]);
    g_Whh_p[row*HID + k] = to_tf32(W_hh[orow*HID + k]);
    if (k == 0) g_bp[row] = b_ih[orow] + b_hh[orow];
    if (idx < OUTDIM*HID) g_Wout_p[idx] = to_tf32(W_out[idx]);
}

// ------------- pre-GEMM: g_xg[m][g] = x[m][:] . Wih_p[g][:]  (m = s*N+n flat) -------------
__global__ void __launch_bounds__(256, 2) xg_gemm_kernel(const float* __restrict__ x) {
    extern __shared__ float sm[];
    float* sA = sm;                 // [128][XPITCH]
    float* sB = sm + 128*XPITCH;    // [64][XPITCH]
    const int tid = threadIdx.x;
    const int m0 = blockIdx.x*128;
    const int n0 = blockIdx.y*64;

    const float* xr = x + (size_t)m0*HID;
    for (int e = tid; e < 128*32; e += 256) {
        int r = e >> 5, c4 = e & 31;
        float4 v = *(const float4*)(xr + (size_t)r*HID + c4*4);
        float* d = &sA[r*XPITCH + c4*4];
        d[0]=to_tf32(v.x); d[1]=to_tf32(v.y); d[2]=to_tf32(v.z); d[3]=to_tf32(v.w);
    }
    for (int e = tid; e < 64*32; e += 256) {
        int r = e >> 5, c4 = e & 31;
        *(float4*)&sB[r*XPITCH + c4*4] = *(const float4*)(g_Wih_p + (size_t)(n0+r)*HID + c4*4);
    }
    __syncthreads();

    const int w = tid >> 5;
    const int wm = w & 3, wn = w >> 2;          // 4x2 warp grid
    wmma::fragment<wmma::accumulator,16,16,8,float> c[2][2];
    #pragma unroll
    for (int i=0;i<2;i++) { wmma::fill_fragment(c[i][0],0.f); wmma::fill_fragment(c[i][1],0.f); }

    #pragma unroll
    for (int k = 0; k < HID; k += 8) {
        wmma::fragment<wmma::matrix_a,16,16,8,wmma::precision::tf32,wmma::row_major> a0,a1;
        wmma::fragment<wmma::matrix_b,16,16,8,wmma::precision::tf32,wmma::col_major> b0,b1;
        wmma::load_matrix_sync(a0, &sA[(wm*32     )*XPITCH + k], XPITCH);
        wmma::load_matrix_sync(a1, &sA[(wm*32 + 16)*XPITCH + k], XPITCH);
        wmma::load_matrix_sync(b0, &sB[(wn*32     )*XPITCH + k], XPITCH);
        wmma::load_matrix_sync(b1, &sB[(wn*32 + 16)*XPITCH + k], XPITCH);
        wmma::mma_sync(c[0][0], a0, b0, c[0][0]);
        wmma::mma_sync(c[0][1], a0, b1, c[0][1]);
        wmma::mma_sync(c[1][0], a1, b0, c[1][0]);
        wmma::mma_sync(c[1][1], a1, b1, c[1][1]);
    }
    #pragma unroll
    for (int i=0;i<2;i++)
        #pragma unroll
        for (int j=0;j<2;j++)
            wmma::store_matrix_sync(&g_xg[(size_t)(m0 + wm*32 + i*16)*G4 + n0 + wn*32 + j*16],
                                    c[i][j], G4, wmma::mem_row_major);
}

// ---------------- persistent recurrence: K=128 (h only), acc init from g_xg ----------------
// Grid (32, 4), cluster (1,4,1), 512 threads = 16 warps.
// Warps 0-7 (group A): k 0..63, acc preloaded from g_xg. Warps 8-15 (B): k 64..127, acc=0.
// Parks gate-major into sPA/sPB -> conflict-free epilogue. h exchanged via g_hist + cluster sync.
__global__ void __launch_bounds__(512) __cluster_dims__(1, 4, 1)
lstm_persist_kernel() {
    extern __shared__ float sm[];
    float* sW    = sm + F_W;
    float* sAh   = sm + F_AH;
    float* sPA   = sm + F_PA;
    float* sPB   = sm + F_PB;
    float* sBias = sm + F_BIAS;

    const int tid = threadIdx.x;
    const int wid = tid >> 5;
    const int nb  = blockIdx.x;
    const int hb  = blockIdx.y;
    const int n0  = nb*64;

    // one-time: W_hh slice + bias
    for (int e = tid; e < 128*32; e += 512) {
        int r = e >> 5, k4 = e & 31;
        *(float4*)&sW[r*WP + k4*4] = *(const float4*)(g_Whh_p + (size_t)(hb*128 + r)*HID + k4*4);
    }
    if (tid < 128) sBias[tid] = g_bp[hb*128 + tid];

    const bool grpA = (wid < 8);
    const int  w8 = wid & 7;
    const int  wm = w8 & 1;                     // 2 warp-rows (samples)
    const int  wn = w8 >> 1;                    // 4 warp-cols (gate rows)

    const int n_l = tid & 63;                   // epilogue: owned sample
    const int jg  = tid >> 6;                   // epilogue: j = jg*4 + q

    float c_reg[4] = {0.f, 0.f, 0.f, 0.f};

    wmma::fragment<wmma::accumulator,16,16,8,float> cfr[2][2];
    const float* xg_base = g_xg + (size_t)n0*G4 + hb*128;

    if (grpA) {                                 // acc(s=0) = xg(0)
        #pragma unroll
        for (int i=0;i<2;i++)
            #pragma unroll
            for (int j=0;j<2;j++)
                wmma::load_matrix_sync(cfr[i][j],
                    xg_base + (size_t)(wm*32 + i*16)*G4 + wn*32 + j*16,
                    G4, wmma::mem_row_major);
    }
    __syncthreads();                            // sW/sBias visible

    float b_i[4], b_f[4], b_g[4], b_o[4];       // bias -> registers, once
    #pragma unroll
    for (int q = 0; q < 4; q++) {
        int j = jg*4 + q;
        b_i[q] = sBias[      j];
        b_f[q] = sBias[ 32 + j];
        b_g[q] = sBias[ 64 + j];
        b_o[q] = sBias[ 96 + j];
    }

    for (int s = 0; s < S_LEN; s++) {
        // ---- stage h(s-1) (hist pre-tf32-rounded; straight copy) ----
        if (s > 0) {
            const float* hp = g_hist + (size_t)(s-1)*NH + (size_t)n0*HID;
            #pragma unroll
            for (int i = 0; i < 4; i++) {
                int e = tid + i*512, r = e >> 5, k4 = e & 31;
                *(float4*)&sAh[r*WP + k4*4] = *(const float4*)(hp + (size_t)r*HID + k4*4);
            }
        } else {
            float4 z = make_float4(0.f, 0.f, 0.f, 0.f);
            #pragma unroll
            for (int i = 0; i < 4; i++) {
                int e = tid + i*512, r = e >> 5, k4 = e & 31;
                *(float4*)&sAh[r*WP + k4*4] = z;
            }
        }
        __syncthreads();

        // ---- GEMM: my K-half over h ----
        if (!grpA) {
            #pragma unroll
            for (int i=0;i<2;i++) { wmma::fill_fragment(cfr[i][0],0.f); wmma::fill_fragment(cfr[i][1],0.f); }
        }
        const int k0 = grpA ? 0 : 64;
        #pragma unroll
        for (int kk = 0; kk < 64; kk += 8) {
            const int k = k0 + kk;
            wmma::fragment<wmma::matrix_a,16,16,8,wmma::precision::tf32,wmma::row_major> a0,a1;
            wmma::fragment<wmma::matrix_b,16,16,8,wmma::precision::tf32,wmma::col_major> b0,b1;
            wmma::load_matrix_sync(a0, &sAh[(wm*32     )*WP + k], WP);
            wmma::load_matrix_sync(a1, &sAh[(wm*32 + 16)*WP + k], WP);
            wmma::load_matrix_sync(b0, &sW [(wn*32     )*WP + k], WP);
            wmma::load_matrix_sync(b1, &sW [(wn*32 + 16)*WP + k], WP);
            wmma::mma_sync(cfr[0][0], a0, b0, cfr[0][0]);
            wmma::mma_sync(cfr[0][1], a0, b1, cfr[0][1]);
            wmma::mma_sync(cfr[1][0], a1, b0, cfr[1][0]);
            wmma::mma_sync(cfr[1][1], a1, b1, cfr[1][1]);
        }

        // ---- park gate-major (col_major store): park[gate_row][sample] ----
        float* park = grpA ? sPA : sPB;
        #pragma unroll
        for (int i=0;i<2;i++)
            #pragma unroll
            for (int j=0;j<2;j++)
                wmma::store_matrix_sync(&park[(wn*32 + j*16)*PP + wm*32 + i*16],
                                        cfr[i][j], PP, wmma::mem_col_major);

        // ---- prefetch acc(s+1) = xg(s+1) (group A); DRAM latency hides under epilogue+staging ----
        if (grpA) {
            int sn = (s + 1 < S_LEN) ? s + 1 : s;
            const float* xp = xg_base + (size_t)sn*NBATCH*G4;
            #pragma unroll
            for (int i=0;i<2;i++)
                #pragma unroll
                for (int j=0;j<2;j++)
                    wmma::load_matrix_sync(cfr[i][j],
                        xp + (size_t)(wm*32 + i*16)*G4 + wn*32 + j*16,
                        G4, wmma::mem_row_major);
        }
        __syncthreads();                        // parks visible

        // ---- elementwise LSTM: conflict-free gate-major reads; c in regs ----
        {
            float hq[4];
            #pragma unroll
            for (int q = 0; q < 4; q++) {
                int j = jg*4 + q;
                float iv = sPA[(      j)*PP + n_l] + sPB[(      j)*PP + n_l] + b_i[q];
                float fv = sPA[( 32 + j)*PP + n_l] + sPB[( 32 + j)*PP + n_l] + b_f[q];
                float gv = sPA[( 64 + j)*PP + n_l] + sPB[( 64 + j)*PP + n_l] + b_g[q];
                float ov = sPA[( 96 + j)*PP + n_l] + sPB[( 96 + j)*PP + n_l] + b_o[q];
                float cc = fsigm(fv)*c_reg[q] + fsigm(iv)*ftanh(gv);
                c_reg[q] = cc;
                hq[q] = to_tf32(fsigm(ov)*ftanh(cc));
            }
            float* hp = g_hist + (size_t)s*NH + (size_t)(n0 + n_l)*HID + hb*32 + jg*4;
            *(float4*)hp = make_float4(hq[0], hq[1], hq[2], hq[3]);
        }

        CLUSTER_SYNC();                         // release hist[s] to hb-peers; step barrier
    }
}

// ------------- projection: out[m][o] = hist[m][:] . W_out[o][:] + b_out[o] -------------
__global__ void __launch_bounds__(256, 2) proj_kernel(const float* __restrict__ b_out,
                                                      float* __restrict__ out) {
    extern __shared__ float sm[];
    float* sA = sm;                 // [128][XPITCH] hist tile; reused as park
    float* sB = sm + 128*XPITCH;    // [64][XPITCH]  W_out slice
    const int tid = threadIdx.x;
    const int m0 = blockIdx.x*128;
    const int n0 = blockIdx.y*64;

    for (int e = tid; e < 128*32; e += 256) {
        int r = e >> 5, c4 = e & 31;
        *(float4*)&sA[r*XPITCH + c4*4] = *(const float4*)(g_hist + (size_t)(m0+r)*HID + c4*4);
    }
    for (int e = tid; e < 64*32; e += 256) {
        int r = e >> 5, c4 = e & 31;
        *(float4*)&sB[r*XPITCH + c4*4] = *(const float4*)(g_Wout_p + (size_t)(n0+r)*HID + c4*4);
    }
    __syncthreads();

    const int w = tid >> 5;
    const int wm = w & 3, wn = w >> 2;
    wmma::fragment<wmma::accumulator,16,16,8,float> c[2][2];
    #pragma unroll
    for (int i=0;i<2;i++) { wmma::fill_fragment(c[i][0],0.f); wmma::fill_fragment(c[i][1],0.f); }

    #pragma unroll
    for (int k = 0; k < HID; k += 8) {
        wmma::fragment<wmma::matrix_a,16,16,8,wmma::precision::tf32,wmma::row_major> a0,a1;
        wmma::fragment<wmma::matrix_b,16,16,8,wmma::precision::tf32,wmma::col_major> b0,b1;
        wmma::load_matrix_sync(a0, &sA[(wm*32     )*XPITCH + k], XPITCH);
        wmma::load_matrix_sync(a1, &sA[(wm*32 + 16)*XPITCH + k], XPITCH);
        wmma::load_matrix_sync(b0, &sB[(wn*32     )*XPITCH + k], XPITCH);
        wmma::load_matrix_sync(b1, &sB[(wn*32 + 16)*XPITCH + k], XPITCH);
        wmma::mma_sync(c[0][0], a0, b0, c[0][0]);
        wmma::mma_sync(c[0][1], a0, b1, c[0][1]);
        wmma::mma_sync(c[1][0], a1, b0, c[1][0]);
        wmma::mma_sync(c[1][1], a1, b1, c[1][1]);
    }
    __syncthreads();
    #pragma unroll
    for (int i=0;i<2;i++)
        #pragma unroll
        for (int j=0;j<2;j++)
            wmma::store_matrix_sync(&sA[(wm*32 + i*16)*XPITCH + wn*32 + j*16],
                                    c[i][j], XPITCH, wmma::mem_row_major);
    __syncthreads();

    for (int e = tid; e < 128*16; e += 256) {
        int r = e >> 4, c4 = e & 15;
        const float* p = &sA[r*XPITCH + c4*4];
        const float* b = &b_out[n0 + c4*4];
        float4 v = make_float4(p[0]+b[0], p[1]+b[1], p[2]+b[2], p[3]+b[3]);
        *(float4*)&out[(size_t)(m0 + r)*OUTDIM + n0 + c4*4] = v;
    }
}

extern "C" void kernel_launch(void* const* d_in, const int* in_sizes, int n_in,
                              void* d_out, int out_size) {
    const float* x     = (const float*)d_in[0];
    const float* W_ih  = (const float*)d_in[1];
    const float* W_hh  = (const float*)d_in[2];
    const float* b_ih  = (const float*)d_in[3];
    const float* b_hh  = (const float*)d_in[4];
    const float* W_out = (const float*)d_in[5];
    const float* b_out = (const float*)d_in[6];
    float* out = (float*)d_out;
    (void)in_sizes; (void)n_in; (void)out_size;

    cudaFuncSetAttribute(xg_gemm_kernel,      cudaFuncAttributeMaxDynamicSharedMemorySize, GEMM_SMEM);
    cudaFuncSetAttribute(lstm_persist_kernel, cudaFuncAttributeMaxDynamicSharedMemorySize, STEP_SMEM);
    cudaFuncSetAttribute(proj_kernel,         cudaFuncAttributeMaxDynamicSharedMemorySize, GEMM_SMEM);

    pack_kernel<<<256, 256>>>(W_ih, W_hh, b_ih, b_hh, W_out);
    xg_gemm_kernel<<<dim3(M_ALL/128, G4/64), 256, GEMM_SMEM>>>(x);

    lstm_persist_kernel<<<dim3(32, 4), 512, STEP_SMEM>>>();

    proj_kernel<<<dim3(M_ALL/128, OUTDIM/64), 256, GEMM_SMEM>>>(b_out, out);
}